// round 4
// baseline (speedup 1.0000x reference)
#include <cuda_runtime.h>
#include <cuda_bf16.h>
#include <math.h>
#include <stdint.h>

#define BB 128
#define NP 8732
#define NO 16
#define NC 21
#define NT 1024
#define NTILES ((NP + NT - 1) / NT)     // 9
#define TILE_F (NT * NC)                 // 21504 floats per tile buffer
#define TILE_B (TILE_F * 4)              // 86016 bytes

// ---------------- globals (zero-init; reset by last CTA each run) ----------------
__device__ double   g_loss_l;
__device__ double   g_loss_c;
__device__ int      g_np;
__device__ unsigned g_done;

// ---------------- smem layout (dynamic) ----------------
// [0, 2*TILE_B)                : conf double buffer
// then: scode[8736] u8, stb float4[16], sarea[16], slab[16], sbest u64[16],
//       dredA[32] dbl, dredB[32] dbl, ured[32] u32, hist[256] u32, wsuf[8] u32,
//       scalars
#define OFF_CODE   (2 * TILE_B)                 // 172032
#define OFF_TB     (OFF_CODE + 8736)            // 180768 (16-aligned)
#define OFF_AREA   (OFF_TB + 256)
#define OFF_LAB    (OFF_AREA + 64)
#define OFF_BEST   (OFF_LAB + 64)               // 8-aligned
#define OFF_DREDA  (OFF_BEST + 128)
#define OFF_DREDB  (OFF_DREDA + 256)
#define OFF_URED   (OFF_DREDB + 256)
#define OFF_HIST   (OFF_URED + 128)
#define OFF_WSUF   (OFF_HIST + 1024)
#define OFF_SCAL   (OFF_WSUF + 32)              // u32 scalars: K, B, Krem
#define SMEM_TOTAL (OFF_SCAL + 64)

// ---------------- helpers ----------------
__device__ __forceinline__ double warp_sum_d(double v) {
#pragma unroll
    for (int o = 16; o > 0; o >>= 1) v += __shfl_down_sync(0xffffffffu, v, o);
    return v;
}
__device__ __forceinline__ unsigned warp_sum_u(unsigned v) {
#pragma unroll
    for (int o = 16; o > 0; o >>= 1) v += __shfl_down_sync(0xffffffffu, v, o);
    return v;
}
__device__ __forceinline__ void cp_async16(uint32_t saddr, const void* g) {
    asm volatile("cp.async.cg.shared.global [%0], [%1], 16;" :: "r"(saddr), "l"(g));
}
__device__ __forceinline__ void cp_commit() {
    asm volatile("cp.async.commit_group;" ::: "memory");
}
template <int N>
__device__ __forceinline__ void cp_wait() {
    asm volatile("cp.async.wait_group %0;" :: "n"(N) : "memory");
}

// ---------------- the single fused kernel ----------------
__global__ void __launch_bounds__(NT, 1)
k_all(const float4* __restrict__ loc4,
      const float* __restrict__ conf,
      const float4* __restrict__ dbox4,
      const float* __restrict__ targets,
      float* __restrict__ out) {
    extern __shared__ __align__(16) char smem[];
    float*              sconf = (float*)smem;
    unsigned char*      scode = (unsigned char*)(smem + OFF_CODE);
    float4*             stb   = (float4*)(smem + OFF_TB);
    float*              sarea = (float*)(smem + OFF_AREA);
    int*                slab  = (int*)(smem + OFF_LAB);
    unsigned long long* sbest = (unsigned long long*)(smem + OFF_BEST);
    double*             dredA = (double*)(smem + OFF_DREDA);
    double*             dredB = (double*)(smem + OFF_DREDB);
    unsigned*           ured  = (unsigned*)(smem + OFF_URED);
    unsigned*           hist  = (unsigned*)(smem + OFF_HIST);
    unsigned*           wsuf  = (unsigned*)(smem + OFF_WSUF);
    unsigned*           sscal = (unsigned*)(smem + OFF_SCAL); // [0]=K [1]=bin [2]=Krem

    const int b    = blockIdx.x;
    const int tid  = threadIdx.x;
    const int lane = tid & 31;
    const int warp = tid >> 5;
    const uint32_t sconf_s = (uint32_t)__cvta_generic_to_shared(sconf);
    const size_t cbase = (size_t)b * NP * NC;

    // ---- prefetch conf tiles 0 and 1 (overlaps with match phase) ----
    {
        const float4* src0 = (const float4*)(conf + cbase);
        for (int i = tid; i < TILE_F / 4; i += NT)
            cp_async16(sconf_s + i * 16, src0 + i);
        cp_commit();
        const float4* src1 = (const float4*)(conf + cbase + (size_t)TILE_F);
        for (int i = tid; i < TILE_F / 4; i += NT)
            cp_async16(sconf_s + TILE_B + i * 16, src1 + i);
        cp_commit();
    }

    // ---- load targets ----
    if (tid < NO) {
        const float* tr = targets + ((size_t)b * NO + tid) * 5;
        float x1 = tr[0], y1 = tr[1], x2 = tr[2], y2 = tr[3];
        stb[tid] = make_float4(x1, y1, x2, y2);
        sarea[tid] = (x2 - x1) * (y2 - y1);
        slab[tid] = (int)tr[4];
        sbest[tid] = 0ULL;
    }
    __syncthreads();

    // ---- phase 1: jaccard match ----
#pragma unroll
    for (int k = 0; k < NTILES; k++) {
        const int p = k * NT + tid;
        const bool valid = (p < NP);
        const int pc = valid ? p : (NP - 1);
        float4 d = dbox4[pc];
        float px1 = d.x - d.z * 0.5f, py1 = d.y - d.w * 0.5f;
        float px2 = d.x + d.z * 0.5f, py2 = d.y + d.w * 0.5f;
        float pa = (px2 - px1) * (py2 - py1);
        float bestv = -1.0f;
        int   bestt = 0;
        const unsigned long long invp = valid ? (unsigned long long)(~(unsigned)p) : 0ULL;
#pragma unroll
        for (int t = 0; t < NO; t++) {
            float4 tb = stb[t];
            float iw = fmaxf(fminf(tb.z, px2) - fmaxf(tb.x, px1), 0.0f);
            float ih = fmaxf(fminf(tb.w, py2) - fmaxf(tb.y, py1), 0.0f);
            float inter = iw * ih;
            float iou = inter / (sarea[t] + pa - inter);
            if (iou > bestv) { bestv = iou; bestt = t; }  // strict >: first-idx tiebreak
            unsigned ioubits = valid ? __float_as_uint(iou) : 0u;
            unsigned wmax = __reduce_max_sync(0xffffffffu, ioubits);
            unsigned ball = __ballot_sync(0xffffffffu, ioubits == wmax);
            if (lane == __ffs(ball) - 1) {   // lowest lane among ties => lowest p
                unsigned long long key = ((unsigned long long)wmax << 32) | invp;
                if (key > sbest[t]) atomicMax(&sbest[t], key);
            }
        }
        if (valid) scode[p] = (bestv >= 0.5f) ? (unsigned char)(bestt + 1) : 0;
    }
    __syncthreads();

    // ---- override: best prior per truth forced positive (ascending t = last wins) ----
    if (tid == 0) {
        for (int t = 0; t < NO; t++) {
            unsigned p = ~(unsigned)(sbest[t] & 0xffffffffu);
            scode[p] = (unsigned char)(t + 1);
        }
    }
    __syncthreads();

    // ---- phase 2: CE + smooth-L1, double-buffered conf tiles ----
    double l_l = 0.0, l_c = 0.0;
    unsigned npos = 0;
    unsigned u[NTILES];   // hnm bits, register-resident for topk

#pragma unroll
    for (int k = 0; k < NTILES; k++) {
        cp_wait<1>();          // tile k resident in buf[k&1]
        __syncthreads();

        const int p = k * NT + tid;
        const int nrows = min(NT, NP - k * NT);
        u[k] = 0u;
        if (tid < nrows) {
            const int code = scode[p];
            const bool pos = (code != 0);
            const int t = code - 1;
            const int cls = pos ? (slab[t] + 1) : 0;

            const float* v = sconf + (k & 1) * TILE_F + tid * NC;  // stride 21: conflict-free
            float m = v[0];
#pragma unroll
            for (int i = 1; i < NC; i++) m = fmaxf(m, v[i]);
            float s = 0.0f;
#pragma unroll
            for (int i = 0; i < NC; i++) s += __expf(v[i] - m);
            float ce = __logf(s) + m - v[cls];

            if (pos) {
                npos++;
                l_c += (double)ce;
                float4 d = dbox4[p];
                float4 tb = stb[t];
                float lt0 = ((tb.x + tb.z) * 0.5f - d.x) / (0.1f * d.z);
                float lt1 = ((tb.y + tb.w) * 0.5f - d.y) / (0.1f * d.w);
                float lt2 = __logf((tb.z - tb.x) / d.z) / 0.2f;
                float lt3 = __logf((tb.w - tb.y) / d.w) / 0.2f;
                float4 ld = loc4[(size_t)b * NP + p];
                float dv[4] = {ld.x - lt0, ld.y - lt1, ld.z - lt2, ld.w - lt3};
                float acc = 0.0f;
#pragma unroll
                for (int i = 0; i < 4; i++) {
                    float ad = fabsf(dv[i]);
                    acc += (ad < 1.0f) ? 0.5f * dv[i] * dv[i] : (ad - 0.5f);
                }
                l_l += (double)acc;
            } else {
                u[k] = __float_as_uint(ce);
            }
        }
        __syncthreads();       // buf[k&1] consumed; safe to refill

        // issue tile k+2 into buf[k&1]; ALWAYS commit (keeps pending-group count = 2)
        const int kn = k + 2;
        if (kn < NTILES) {
            const int nr = min(NT, NP - kn * NT);
            const int n4 = nr * NC / 4;
            const float4* src = (const float4*)(conf + cbase + (size_t)kn * TILE_F);
            for (int i = tid; i < n4; i += NT)
                cp_async16(sconf_s + (k & 1) * TILE_B + i * 16, src + i);
        }
        cp_commit();
    }

    // ---- npos reduce -> K ----
    {
        unsigned wn = warp_sum_u(npos);
        if (lane == 0) ured[warp] = wn;
        __syncthreads();
        if (tid == 0) {
            unsigned tot = 0;
            for (int w = 0; w < 32; w++) tot += ured[w];
            sscal[0] = tot;
        }
        __syncthreads();
    }
    const unsigned npos_b = sscal[0];
    const unsigned K = min(3u * npos_b, (unsigned)NP);

    // ---- phase 3: top-K sum of hnm (radix-256 select on registers) ----
    double topk_sum = 0.0;   // valid on tid==0
    if (K > 0) {
        unsigned prefix = 0, Krem = K;
#pragma unroll
        for (int pass = 0; pass < 4; pass++) {
            const int shift = 24 - pass * 8;
            if (tid < 256) hist[tid] = 0;
            __syncthreads();
#pragma unroll
            for (int k = 0; k < NTILES; k++) {
                bool match = (pass == 0) || ((u[k] >> (shift + 8)) == prefix);
                unsigned bin = match ? ((u[k] >> shift) & 0xFFu) : 0xFFFFFFFFu;
                unsigned mk = __match_any_sync(0xffffffffu, bin);
                if (match && lane == (__ffs(mk) - 1))
                    atomicAdd(&hist[bin], (unsigned)__popc(mk));
            }
            __syncthreads();
            unsigned v = 0, s = 0;
            if (tid < 256) {
                v = hist[tid];
                s = v;
#pragma unroll
                for (int off = 1; off < 32; off <<= 1) {
                    unsigned w = __shfl_down_sync(0xffffffffu, s, off);
                    if (lane + off < 32) s += w;
                }
                if (lane == 0) wsuf[warp] = s;
            }
            __syncthreads();
            if (tid == 0) {
                unsigned acc = 0;
                for (int w = 7; w >= 0; w--) { unsigned t2 = wsuf[w]; wsuf[w] = acc; acc += t2; }
            }
            __syncthreads();
            if (tid < 256) {
                unsigned exc = (s - v) + wsuf[warp];
                if (exc < Krem && Krem <= exc + v) { sscal[1] = (unsigned)tid; sscal[2] = Krem - exc; }
            }
            __syncthreads();
            prefix = (prefix << 8) | sscal[1];
            Krem = sscal[2];
        }

        const unsigned T = prefix;   // bits of K-th largest (all hnm >= 0)
        double sum = 0.0;
        unsigned cgt = 0;
#pragma unroll
        for (int k = 0; k < NTILES; k++)
            if (u[k] > T) { sum += (double)__uint_as_float(u[k]); cgt++; }
        sum = warp_sum_d(sum);
        cgt = warp_sum_u(cgt);
        if (lane == 0) { dredA[warp] = sum; ured[warp] = cgt; }
        __syncthreads();
        if (tid == 0) {
            double ts = 0.0; unsigned tc = 0;
            for (int w = 0; w < 32; w++) { ts += dredA[w]; tc += ured[w]; }
            ts += (double)(K - tc) * (double)__uint_as_float(T);
            topk_sum = ts;
        }
        __syncthreads();
    }

    // ---- phase 4: block reduce losses, global atomics, last-CTA finalize ----
    {
        double wll = warp_sum_d(l_l);
        double wlc = warp_sum_d(l_c);
        if (lane == 0) { dredA[warp] = wll; dredB[warp] = wlc; }
        __syncthreads();
        if (tid == 0) {
            double tll = 0.0, tlc = 0.0;
            for (int w = 0; w < 32; w++) { tll += dredA[w]; tlc += dredB[w]; }
            tlc += topk_sum;
            atomicAdd(&g_loss_l, tll);
            atomicAdd(&g_loss_c, tlc);
            atomicAdd(&g_np, (int)npos_b);
            __threadfence();
            unsigned ticket = atomicAdd(&g_done, 1u);
            if (ticket == BB - 1) {
                __threadfence();
                double N = (double)(*(volatile int*)&g_np);
                double ll = *(volatile double*)&g_loss_l;
                double lc = *(volatile double*)&g_loss_c;
                out[0] = (float)(ll / N);
                out[1] = (float)(lc / N);
                // reset for next graph replay
                g_loss_l = 0.0;
                g_loss_c = 0.0;
                g_np = 0;
                __threadfence();
                g_done = 0;
            }
        }
    }
}

// ---------------- launch ----------------
extern "C" void kernel_launch(void* const* d_in, const int* in_sizes, int n_in,
                              void* d_out, int out_size) {
    const float4* loc4    = (const float4*)d_in[0];
    const float*  conf    = (const float*)d_in[1];
    const float4* dbox4   = (const float4*)d_in[2];
    const float*  targets = (const float*)d_in[3];
    float* out = (float*)d_out;

    cudaFuncSetAttribute(k_all, cudaFuncAttributeMaxDynamicSharedMemorySize, SMEM_TOTAL);
    k_all<<<BB, NT, SMEM_TOTAL>>>(loc4, conf, dbox4, targets, out);
}

// round 6
// speedup vs baseline: 1.3963x; 1.3963x over previous
#include <cuda_runtime.h>
#include <cuda_bf16.h>
#include <math.h>
#include <stdint.h>

#define BB 128
#define NP 8732
#define NO 16
#define NC 21
#define PBLK 256
#define NXB ((NP + PBLK - 1) / PBLK)   // 35
#define TKT 1024                        // k_topk threads
#define EPT ((NP + TKT - 1) / TKT)      // 9 elements per thread

// ---------------- scratch (static __device__; zero-init; self-resetting) ----------------
__device__ unsigned long long g_best_prior[BB * NO];   // reset in k_topk
__device__ unsigned char      g_code[(size_t)BB * NP]; // t+1 if positive else 0
__device__ float              g_hnm[(size_t)BB * NP];
__device__ int                g_numpos[BB];            // reset in k_topk
__device__ int                g_np;                    // reset by last topk block
__device__ double             g_loss_l;                // reset by last topk block
__device__ double             g_loss_c;                // reset by last topk block
__device__ unsigned           g_done;                  // reset by last topk block

// ---------------- helpers ----------------
__device__ __forceinline__ double warp_sum_d(double v) {
#pragma unroll
    for (int o = 16; o > 0; o >>= 1) v += __shfl_down_sync(0xffffffffu, v, o);
    return v;
}
__device__ __forceinline__ unsigned warp_sum_u(unsigned v) {
#pragma unroll
    for (int o = 16; o > 0; o >>= 1) v += __shfl_down_sync(0xffffffffu, v, o);
    return v;
}

// ---------------- K1: jaccard match ----------------
// grid (NXB, BB), block 256
__global__ void k_match(const float4* __restrict__ dbox4,
                        const float* __restrict__ targets) {
    __shared__ float4 stb[NO];
    __shared__ float  sarea[NO];
    __shared__ unsigned long long sbest[NO];
    const int b = blockIdx.y;
    const int tid = threadIdx.x;
    const int lane = tid & 31;

    if (tid < NO) {
        const float* tr = targets + ((size_t)b * NO + tid) * 5;
        float x1 = tr[0], y1 = tr[1], x2 = tr[2], y2 = tr[3];
        stb[tid] = make_float4(x1, y1, x2, y2);
        sarea[tid] = (x2 - x1) * (y2 - y1);
        sbest[tid] = 0ULL;
    }
    __syncthreads();

    const int p = blockIdx.x * PBLK + tid;
    const bool valid = (p < NP);
    const int pc = valid ? p : (NP - 1);
    float4 d = dbox4[pc];
    float px1 = d.x - d.z * 0.5f, py1 = d.y - d.w * 0.5f;
    float px2 = d.x + d.z * 0.5f, py2 = d.y + d.w * 0.5f;
    float pa = (px2 - px1) * (py2 - py1);
    float bestv = 0.0f;           // strict >: all-zero column -> t=0, matches argmax
    int   bestt = 0;
    const unsigned long long invp = valid ? (unsigned long long)(~(unsigned)p) : 0ULL;

#pragma unroll
    for (int t = 0; t < NO; t++) {
        float4 tb = stb[t];
        float iw = fmaxf(fminf(tb.z, px2) - fmaxf(tb.x, px1), 0.0f);
        float ih = fmaxf(fminf(tb.w, py2) - fmaxf(tb.y, py1), 0.0f);
        float inter = iw * ih;
        // fast divide: 1 MUFU.RCP + mul (threshold flips are measure-zero on random data)
        float iou = __fdividef(inter, sarea[t] + pa - inter);
        if (iou > bestv) { bestv = iou; bestt = t; }   // first-index tiebreak
        unsigned ioubits = valid ? __float_as_uint(iou) : 0u;
        unsigned wmax = __reduce_max_sync(0xffffffffu, ioubits);
        if (wmax) {   // skip leader-election entirely when no lane intersects truth t
            unsigned ball = __ballot_sync(0xffffffffu, ioubits == wmax);
            if (lane == __ffs(ball) - 1) {   // lowest lane among ties => lowest p
                unsigned long long key = ((unsigned long long)wmax << 32) | invp;
                if (key > sbest[t]) atomicMax(&sbest[t], key);
            }
        }
    }
    if (valid)
        g_code[(size_t)b * NP + p] = (bestv >= 0.5f) ? (unsigned char)(bestt + 1) : 0;
    __syncthreads();
    if (tid < NO && sbest[tid]) atomicMax(&g_best_prior[b * NO + tid], sbest[tid]);
}

// ---------------- K2: main loss (override folded in; CE + smooth-L1) ----------------
// grid (NXB, BB), block 256
__global__ void k_loss(const float4* __restrict__ loc4,
                       const float* __restrict__ conf,
                       const float4* __restrict__ dbox4,
                       const float* __restrict__ targets) {
    __shared__ __align__(16) float sconf[PBLK * NC];   // 21504 B
    __shared__ float4 stb[NO];
    __shared__ int    slab[NO];
    __shared__ int    sprior[NO];
    __shared__ double s_ll[8], s_lc[8];
    __shared__ unsigned s_np[8];

    const int b = blockIdx.y;
    const int tid = threadIdx.x;
    const int p0 = blockIdx.x * PBLK;
    const int nrows = min(PBLK, NP - p0);

    if (tid < NO) {
        const float* tr = targets + ((size_t)b * NO + tid) * 5;
        stb[tid] = make_float4(tr[0], tr[1], tr[2], tr[3]);
        slab[tid] = (int)tr[4];
        unsigned long long key = g_best_prior[b * NO + tid];
        sprior[tid] = (int)(~(unsigned)(key & 0xffffffffu));   // key==0 -> -1, never matches
    }

    // stage conf tile via coalesced float4 (base 16B-aligned; nrows always mult of 4)
    const size_t base = ((size_t)b * NP + p0) * NC;
    {
        const float4* src = (const float4*)(conf + base);
        float4* dst = (float4*)sconf;
        const int n4 = nrows * NC / 4;
        for (int i = tid; i < n4; i += PBLK)
            dst[i] = src[i];
    }
    __syncthreads();

    double l_l = 0.0, l_c = 0.0;
    unsigned npos = 0;

    if (tid < nrows) {
        const int p = p0 + tid;
        const size_t ip = (size_t)b * NP + p;
        int code = g_code[ip];
#pragma unroll
        for (int t = 0; t < NO; t++)
            if (sprior[t] == p) code = t + 1;   // ascending t => last wins
        const bool pos = (code != 0);
        const int t = code - 1;
        const int cls = pos ? (slab[t] + 1) : 0;

        const float* v = sconf + tid * NC;   // stride 21 (odd): bank-conflict-free
        float m = v[0];
#pragma unroll
        for (int i = 1; i < NC; i++) m = fmaxf(m, v[i]);
        float s = 0.0f;
#pragma unroll
        for (int i = 0; i < NC; i++) s += __expf(v[i] - m);
        float ce = __logf(s) + m - v[cls];

        g_hnm[ip] = pos ? 0.0f : ce;

        if (pos) {
            npos = 1;
            l_c = (double)ce;
            float4 d = dbox4[p];
            float4 tb = stb[t];
            float lt0 = ((tb.x + tb.z) * 0.5f - d.x) / (0.1f * d.z);
            float lt1 = ((tb.y + tb.w) * 0.5f - d.y) / (0.1f * d.w);
            float lt2 = __logf((tb.z - tb.x) / d.z) / 0.2f;
            float lt3 = __logf((tb.w - tb.y) / d.w) / 0.2f;
            float4 ld = loc4[ip];
            float dv[4] = {ld.x - lt0, ld.y - lt1, ld.z - lt2, ld.w - lt3};
            float acc = 0.0f;
#pragma unroll
            for (int i = 0; i < 4; i++) {
                float ad = fabsf(dv[i]);
                acc += (ad < 1.0f) ? 0.5f * dv[i] * dv[i] : (ad - 0.5f);
            }
            l_l = (double)acc;
        }
    }

    double wll = warp_sum_d(l_l);
    double wlc = warp_sum_d(l_c);
    unsigned wnp = warp_sum_u(npos);
    const int warp = tid >> 5, lane = tid & 31;
    if (lane == 0) { s_ll[warp] = wll; s_lc[warp] = wlc; s_np[warp] = wnp; }
    __syncthreads();
    if (tid == 0) {
        double tll = 0.0, tlc = 0.0; unsigned tnp = 0;
        for (int w = 0; w < 8; w++) { tll += s_ll[w]; tlc += s_lc[w]; tnp += s_np[w]; }
        if (tll != 0.0) atomicAdd(&g_loss_l, tll);
        if (tlc != 0.0) atomicAdd(&g_loss_c, tlc);
        if (tnp) atomicAdd(&g_numpos[b], (int)tnp);
    }
}

// ---------------- K3: top-K sum + last-block finalize ----------------
// grid BB blocks, 1024 threads; register-resident radix-256 select
__global__ void __launch_bounds__(TKT, 1) k_topk(float* __restrict__ out) {
    __shared__ unsigned hist[256];
    __shared__ unsigned wsuf[8];
    __shared__ unsigned s_B, s_Krem;
    __shared__ int      s_npos;
    __shared__ double   ssum[TKT / 32];
    __shared__ unsigned scnt[TKT / 32];

    const int b = blockIdx.x;
    const int tid = threadIdx.x;
    const int lane = tid & 31, warp = tid >> 5;

    if (tid < NO) g_best_prior[b * NO + tid] = 0ULL;   // reset for next replay

    // RACE FIX: single reader+resetter, then barrier, then broadcast via smem.
    if (tid == 0) { s_npos = g_numpos[b]; g_numpos[b] = 0; }

    unsigned u[EPT];
#pragma unroll
    for (int k = 0; k < EPT; k++) {
        int i = tid + k * TKT;
        u[k] = (i < NP) ? __float_as_uint(g_hnm[(size_t)b * NP + i]) : 0u;
    }
    __syncthreads();
    const int npos_b = s_npos;
    const int K = min(3 * npos_b, NP);

    double topk_sum = 0.0;   // valid on tid 0
    if (K > 0) {
        unsigned prefix = 0, Krem = (unsigned)K;
#pragma unroll
        for (int pass = 0; pass < 4; pass++) {
            const int shift = 24 - pass * 8;
            if (tid < 256) hist[tid] = 0;
            __syncthreads();
#pragma unroll
            for (int k = 0; k < EPT; k++) {
                bool match = (pass == 0) || ((u[k] >> (shift + 8)) == prefix);
                unsigned bin = match ? ((u[k] >> shift) & 0xFFu) : 0xFFFFFFFFu;
                unsigned mk = __match_any_sync(0xffffffffu, bin);
                if (match && lane == (__ffs(mk) - 1))
                    atomicAdd(&hist[bin], (unsigned)__popc(mk));
            }
            __syncthreads();
            unsigned v = 0, s = 0;
            if (tid < 256) {
                v = hist[tid];
                s = v;
#pragma unroll
                for (int off = 1; off < 32; off <<= 1) {
                    unsigned w = __shfl_down_sync(0xffffffffu, s, off);
                    if (lane + off < 32) s += w;
                }
                if (lane == 0) wsuf[warp] = s;
            }
            __syncthreads();
            if (tid == 0) {
                unsigned acc = 0;
                for (int w = 7; w >= 0; w--) { unsigned t2 = wsuf[w]; wsuf[w] = acc; acc += t2; }
            }
            __syncthreads();
            if (tid < 256) {
                unsigned exc = (s - v) + wsuf[warp];
                if (exc < Krem && Krem <= exc + v) { s_B = (unsigned)tid; s_Krem = Krem - exc; }
            }
            __syncthreads();
            prefix = (prefix << 8) | s_B;
            Krem = s_Krem;
        }

        const unsigned T = prefix;   // bits of K-th largest (all hnm >= 0)
        double sum = 0.0;
        unsigned cgt = 0;
#pragma unroll
        for (int k = 0; k < EPT; k++)
            if (u[k] > T) { sum += (double)__uint_as_float(u[k]); cgt++; }
        sum = warp_sum_d(sum);
        cgt = warp_sum_u(cgt);
        if (lane == 0) { ssum[warp] = sum; scnt[warp] = cgt; }
        __syncthreads();
        if (tid == 0) {
            double ts = 0.0; unsigned tc = 0;
            for (int w = 0; w < TKT / 32; w++) { ts += ssum[w]; tc += scnt[w]; }
            ts += (double)((unsigned)K - tc) * (double)__uint_as_float(T);
            topk_sum = ts;
        }
    }

    // finalize: every block arrives; last block computes output and resets globals
    if (tid == 0) {
        if (topk_sum != 0.0) atomicAdd(&g_loss_c, topk_sum);
        if (npos_b) atomicAdd(&g_np, npos_b);
        __threadfence();
        unsigned ticket = atomicAdd(&g_done, 1u);
        if (ticket == BB - 1) {
            __threadfence();
            double N  = (double)(*(volatile int*)&g_np);
            double ll = *(volatile double*)&g_loss_l;
            double lc = *(volatile double*)&g_loss_c;
            out[0] = (float)(ll / N);
            out[1] = (float)(lc / N);
            g_loss_l = 0.0;
            g_loss_c = 0.0;
            g_np = 0;
            __threadfence();
            g_done = 0;
        }
    }
}

// ---------------- launch ----------------
extern "C" void kernel_launch(void* const* d_in, const int* in_sizes, int n_in,
                              void* d_out, int out_size) {
    const float4* loc4    = (const float4*)d_in[0];
    const float*  conf    = (const float*)d_in[1];
    const float4* dbox4   = (const float4*)d_in[2];
    const float*  targets = (const float*)d_in[3];
    float* out = (float*)d_out;

    k_match<<<dim3(NXB, BB), PBLK>>>(dbox4, targets);
    k_loss<<<dim3(NXB, BB), PBLK>>>(loc4, conf, dbox4, targets);
    k_topk<<<BB, TKT>>>(out);
}